// round 1
// baseline (speedup 1.0000x reference)
#include <cuda_runtime.h>

// ---------------------------------------------------------------------------
// GCNMixEncoder: 3-layer graph propagation + layer-mean + batched gather.
// Strategy: build CSR per launch (no float atomics), warp-per-row SpMM with
// float4 lanes (L2-resident dense matrix), accumulate gathered outputs
// per-layer directly into d_out.
// ---------------------------------------------------------------------------

#define U_COUNT 100000
#define I_COUNT 50000
#define NN      (U_COUNT + I_COUNT)   // 150000
#define NNZ_C   1600000
#define BATCHQ  4096
#define SCAN_CHUNK 4096
#define N_PAD   151552                 // ceil(NN/4096)*4096

// Static device scratch (allowed; no runtime allocation).
__device__ float g_X[(long long)NN * 128];
__device__ float g_Y[(long long)NN * 128];
__device__ int   g_counts[N_PAD];
__device__ int   g_rowptr[NN + 1];
__device__ int   g_cursor[NN];
__device__ int   g_colS[NNZ_C];
__device__ float g_valS[NNZ_C];

__global__ void k_zero_counts() {
    int i = blockIdx.x * blockDim.x + threadIdx.x;
    if (i < N_PAD) g_counts[i] = 0;
}

// Copy [user_emb; item_emb] into g_X as float4s.
__global__ void k_init_x(const float4* __restrict__ ue, const float4* __restrict__ ie) {
    int i = blockIdx.x * blockDim.x + threadIdx.x;   // float4 index
    const int UQ = U_COUNT * 32;
    const int TQ = NN * 32;
    if (i < UQ)       reinterpret_cast<float4*>(g_X)[i] = ue[i];
    else if (i < TQ)  reinterpret_cast<float4*>(g_X)[i] = ie[i - UQ];
}

__global__ void k_hist(const int* __restrict__ rows) {
    int e = blockIdx.x * blockDim.x + threadIdx.x;
    if (e < NNZ_C) atomicAdd(&g_counts[rows[e]], 1);
}

// Single-block chained exclusive scan over g_counts -> g_rowptr / g_cursor.
// 1024 threads, 4 elems/thread, 37 chunks.
__global__ void k_scan() {
    __shared__ int wsum[32];
    __shared__ int s_carry;
    int t = threadIdx.x, lane = t & 31, wid = t >> 5;
    if (t == 0) s_carry = 0;
    __syncthreads();
    for (int base = 0; base < N_PAD; base += SCAN_CHUNK) {
        int i0 = base + t * 4;
        int4 c = *reinterpret_cast<const int4*>(&g_counts[i0]);
        int p1 = c.x;
        int p2 = p1 + c.y;
        int p3 = p2 + c.z;
        int tot = p3 + c.w;
        int v = tot;
        #pragma unroll
        for (int o = 1; o < 32; o <<= 1) {
            int n = __shfl_up_sync(0xffffffffu, v, o);
            if (lane >= o) v += n;
        }
        if (lane == 31) wsum[wid] = v;
        __syncthreads();
        if (wid == 0) {
            int wv = wsum[lane];
            #pragma unroll
            for (int o = 1; o < 32; o <<= 1) {
                int n = __shfl_up_sync(0xffffffffu, wv, o);
                if (lane >= o) wv += n;
            }
            wsum[lane] = wv;
        }
        __syncthreads();
        int warp_off = wid ? wsum[wid - 1] : 0;
        int excl = s_carry + warp_off + (v - tot);
        if (i0     < NN) { g_rowptr[i0]     = excl;      g_cursor[i0]     = excl;      }
        if (i0 + 1 < NN) { g_rowptr[i0 + 1] = excl + p1; g_cursor[i0 + 1] = excl + p1; }
        if (i0 + 2 < NN) { g_rowptr[i0 + 2] = excl + p2; g_cursor[i0 + 2] = excl + p2; }
        if (i0 + 3 < NN) { g_rowptr[i0 + 3] = excl + p3; g_cursor[i0 + 3] = excl + p3; }
        __syncthreads();
        if (t == 0) s_carry += wsum[31];
        __syncthreads();
    }
    if (threadIdx.x == 0) g_rowptr[NN] = NNZ_C;
}

__global__ void k_scatter(const int* __restrict__ rows, const int* __restrict__ cols,
                          const float* __restrict__ vals) {
    int e = blockIdx.x * blockDim.x + threadIdx.x;
    if (e >= NNZ_C) return;
    int r = rows[e];
    int p = atomicAdd(&g_cursor[r], 1);
    g_colS[p] = cols[e];
    g_valS[p] = vals[e];
}

// Warp-per-row CSR SpMM: dst[r,:] = sum_e val[e] * src[col[e],:]
// dir==0: X->Y ; dir==1: Y->X.
__global__ void k_spmm(int dir) {
    int w = (blockIdx.x * blockDim.x + threadIdx.x) >> 5;
    int lane = threadIdx.x & 31;
    if (w >= NN) return;
    const float4* __restrict__ src =
        dir ? reinterpret_cast<const float4*>(g_Y) : reinterpret_cast<const float4*>(g_X);
    float4* __restrict__ dst =
        dir ? reinterpret_cast<float4*>(g_X) : reinterpret_cast<float4*>(g_Y);
    int start = g_rowptr[w], end = g_rowptr[w + 1];
    float4 acc = make_float4(0.f, 0.f, 0.f, 0.f);
    for (int base = start; base < end; base += 32) {
        int e = base + lane;
        int c = 0; float v = 0.f;
        if (e < end) { c = g_colS[e]; v = g_valS[e]; }
        int cnt = min(32, end - base);
        for (int j = 0; j < cnt; ++j) {
            int   cj = __shfl_sync(0xffffffffu, c, j);
            float vj = __shfl_sync(0xffffffffu, v, j);
            float4 x = __ldg(&src[cj * 32 + lane]);
            acc.x = fmaf(vj, x.x, acc.x);
            acc.y = fmaf(vj, x.y, acc.y);
            acc.z = fmaf(vj, x.z, acc.z);
            acc.w = fmaf(vj, x.w, acc.w);
        }
    }
    dst[w * 32 + lane] = acc;
}

// Gather + 0.25 * add into d_out. which: 0 reads g_X, 1 reads g_Y.
// users/items may be int32 or int64 (JAX x64 ambiguity): detect on device.
__device__ __forceinline__ bool is_i64(const int* p) {
    bool z = true;
    #pragma unroll
    for (int j = 1; j < 64; j += 2) z = z && (p[j] == 0);
    return z;
}

__global__ void k_gather(const int* __restrict__ users, const int* __restrict__ items,
                         float4* __restrict__ out, int which, int init) {
    int w = (blockIdx.x * blockDim.x + threadIdx.x) >> 5;
    int lane = threadIdx.x & 31;
    if (w >= 2 * BATCHQ) return;
    const float4* __restrict__ src =
        which ? reinterpret_cast<const float4*>(g_Y) : reinterpret_cast<const float4*>(g_X);
    int node;
    if (w < BATCHQ) {
        bool w64 = is_i64(users);
        node = w64 ? users[2 * w] : users[w];
    } else {
        int idx = w - BATCHQ;
        bool w64 = is_i64(items);
        node = U_COUNT + (w64 ? items[2 * idx] : items[idx]);
    }
    node = max(0, min(NN - 1, node));
    float4 v = src[node * 32 + lane];
    float4 o = init ? make_float4(0.f, 0.f, 0.f, 0.f) : out[w * 32 + lane];
    o.x += 0.25f * v.x;
    o.y += 0.25f * v.y;
    o.z += 0.25f * v.z;
    o.w += 0.25f * v.w;
    out[w * 32 + lane] = o;
}

extern "C" void kernel_launch(void* const* d_in, const int* in_sizes, int n_in,
                              void* d_out, int out_size) {
    const float4* user_emb = (const float4*)d_in[0];
    const float4* item_emb = (const float4*)d_in[1];
    const float*  adj_vals = (const float*)d_in[2];
    const int*    adj_rows = (const int*)d_in[3];
    const int*    adj_cols = (const int*)d_in[4];
    const int*    users    = (const int*)d_in[5];  // width detected on device
    const int*    items    = (const int*)d_in[6];
    float4*       out      = (float4*)d_out;

    const int T = 256;
    // CSR build
    k_zero_counts<<<(N_PAD + T - 1) / T, T>>>();
    k_init_x<<<(NN * 32 + T - 1) / T, T>>>(user_emb, item_emb);
    k_hist<<<(NNZ_C + T - 1) / T, T>>>(adj_rows);
    k_scan<<<1, 1024>>>();
    k_scatter<<<(NNZ_C + T - 1) / T, T>>>(adj_rows, adj_cols, adj_vals);

    const int GATHER_BLOCKS = (2 * BATCHQ * 32 + T - 1) / T;
    const int SPMM_BLOCKS   = (NN * 32 + T - 1) / T;

    // layer 0 (ego itself)
    k_gather<<<GATHER_BLOCKS, T>>>(users, items, out, /*which=X*/0, /*init=*/1);
    // layer 1: X->Y
    k_spmm<<<SPMM_BLOCKS, T>>>(0);
    k_gather<<<GATHER_BLOCKS, T>>>(users, items, out, 1, 0);
    // layer 2: Y->X
    k_spmm<<<SPMM_BLOCKS, T>>>(1);
    k_gather<<<GATHER_BLOCKS, T>>>(users, items, out, 0, 0);
    // layer 3: X->Y
    k_spmm<<<SPMM_BLOCKS, T>>>(0);
    k_gather<<<GATHER_BLOCKS, T>>>(users, items, out, 1, 0);
}

// round 4
// speedup vs baseline: 1.1722x; 1.1722x over previous
#include <cuda_runtime.h>

// ---------------------------------------------------------------------------
// GCNMixEncoder: 3-layer graph propagation + layer-mean + batched gather.
// R4: R1 architecture (known passing) + parallel scan + no init copy +
// x4-unrolled SpMM inner loop. No host-side statics / symbol addressing.
// ---------------------------------------------------------------------------

#define U_COUNT 100000
#define I_COUNT 50000
#define NN      (U_COUNT + I_COUNT)   // 150000
#define NNZ_C   1600000
#define BATCHQ  4096
#define SCAN_CHUNK 4096
#define N_PAD   151552                 // ceil(NN/4096)*4096
#define NBLK_SCAN (N_PAD / SCAN_CHUNK) // 37

__device__ float g_X[(long long)NN * 128];
__device__ float g_Y[(long long)NN * 128];
__device__ int   g_counts[N_PAD];
__device__ int   g_rowptr[NN + 1];
__device__ int   g_cursor[NN];
__device__ int   g_bsums[64];
__device__ int   g_colS[NNZ_C];
__device__ float g_valS[NNZ_C];

__global__ void k_zero_counts() {
    int i = blockIdx.x * blockDim.x + threadIdx.x;
    if (i < N_PAD) g_counts[i] = 0;
}

__global__ void k_hist(const int* __restrict__ rows) {
    int e = blockIdx.x * blockDim.x + threadIdx.x;
    if (e < NNZ_C) atomicAdd(&g_counts[rows[e]], 1);
}

// Phase 1: block-local exclusive scan of a 4096-elem chunk; total to g_bsums.
__global__ void k_scan_part() {
    __shared__ int wsum[32];
    int b = blockIdx.x, t = threadIdx.x, lane = t & 31, wid = t >> 5;
    int i0 = b * SCAN_CHUNK + t * 4;
    int4 c = *reinterpret_cast<const int4*>(&g_counts[i0]);
    int p1 = c.x;
    int p2 = p1 + c.y;
    int p3 = p2 + c.z;
    int tot = p3 + c.w;
    int v = tot;
    #pragma unroll
    for (int o = 1; o < 32; o <<= 1) {
        int n = __shfl_up_sync(0xffffffffu, v, o);
        if (lane >= o) v += n;
    }
    if (lane == 31) wsum[wid] = v;
    __syncthreads();
    if (wid == 0) {
        int wv = wsum[lane];
        #pragma unroll
        for (int o = 1; o < 32; o <<= 1) {
            int n = __shfl_up_sync(0xffffffffu, wv, o);
            if (lane >= o) wv += n;
        }
        wsum[lane] = wv;
    }
    __syncthreads();
    int warp_off = wid ? wsum[wid - 1] : 0;
    int excl = warp_off + (v - tot);
    if (i0     < NN) g_rowptr[i0]     = excl;
    if (i0 + 1 < NN) g_rowptr[i0 + 1] = excl + p1;
    if (i0 + 2 < NN) g_rowptr[i0 + 2] = excl + p2;
    if (i0 + 3 < NN) g_rowptr[i0 + 3] = excl + p3;
    if (t == 0) g_bsums[b] = wsum[31];
}

// Phase 2: add inter-block offsets (serial sum over <=37 values) + init cursor.
__global__ void k_scan_add() {
    __shared__ int s_off;
    int b = blockIdx.x, t = threadIdx.x;
    if (t == 0) {
        int s = 0;
        for (int j = 0; j < b; ++j) s += g_bsums[j];
        s_off = s;
    }
    __syncthreads();
    int off = s_off;
    int i0 = b * SCAN_CHUNK + t * 4;
    #pragma unroll
    for (int k = 0; k < 4; ++k) {
        int i = i0 + k;
        if (i < NN) {
            int r = g_rowptr[i] + off;
            g_rowptr[i] = r;
            g_cursor[i] = r;
        }
    }
    if (b == 0 && t == 0) g_rowptr[NN] = NNZ_C;
}

__global__ void k_scatter(const int* __restrict__ rows, const int* __restrict__ cols,
                          const float* __restrict__ vals) {
    int e = blockIdx.x * blockDim.x + threadIdx.x;
    if (e >= NNZ_C) return;
    int r = rows[e];
    int p = atomicAdd(&g_cursor[r], 1);
    g_colS[p] = cols[e];
    g_valS[p] = vals[e];
}

// ---------------------------------------------------------------------------
// Warp-per-row CSR SpMM. mode selects source/destination:
//   mode 0: src = [user_emb ; item_emb] (split inputs), dst = g_Y
//   mode 1: src = g_Y, dst = g_X
//   mode 2: src = g_X, dst = g_Y
// ---------------------------------------------------------------------------
__global__ void k_spmm(const float4* __restrict__ embU, const float4* __restrict__ embI,
                       int mode) {
    int w = (blockIdx.x * blockDim.x + threadIdx.x) >> 5;
    int lane = threadIdx.x & 31;
    if (w >= NN) return;

    const float4* srcU;
    const float4* srcI;
    int split;
    float4* dst;
    if (mode == 0) {
        srcU = embU; srcI = embI; split = U_COUNT;
        dst = reinterpret_cast<float4*>(g_Y);
    } else if (mode == 1) {
        srcU = reinterpret_cast<const float4*>(g_Y); srcI = srcU; split = NN;
        dst = reinterpret_cast<float4*>(g_X);
    } else {
        srcU = reinterpret_cast<const float4*>(g_X); srcI = srcU; split = NN;
        dst = reinterpret_cast<float4*>(g_Y);
    }

    int start = g_rowptr[w], end = g_rowptr[w + 1];
    float4 acc = make_float4(0.f, 0.f, 0.f, 0.f);
    for (int base = start; base < end; base += 32) {
        int e = base + lane;
        int c = 0; float v = 0.f;
        if (e < end) { c = g_colS[e]; v = g_valS[e]; }
        int cnt = min(32, end - base);
        int j = 0;
        for (; j + 4 <= cnt; j += 4) {
            int   c0 = __shfl_sync(0xffffffffu, c, j);
            int   c1 = __shfl_sync(0xffffffffu, c, j + 1);
            int   c2 = __shfl_sync(0xffffffffu, c, j + 2);
            int   c3 = __shfl_sync(0xffffffffu, c, j + 3);
            float v0 = __shfl_sync(0xffffffffu, v, j);
            float v1 = __shfl_sync(0xffffffffu, v, j + 1);
            float v2 = __shfl_sync(0xffffffffu, v, j + 2);
            float v3 = __shfl_sync(0xffffffffu, v, j + 3);
            const float4* p0 = (c0 < split) ? (srcU + (long long)c0 * 32)
                                            : (srcI + (long long)(c0 - split) * 32);
            const float4* p1 = (c1 < split) ? (srcU + (long long)c1 * 32)
                                            : (srcI + (long long)(c1 - split) * 32);
            const float4* p2 = (c2 < split) ? (srcU + (long long)c2 * 32)
                                            : (srcI + (long long)(c2 - split) * 32);
            const float4* p3 = (c3 < split) ? (srcU + (long long)c3 * 32)
                                            : (srcI + (long long)(c3 - split) * 32);
            float4 x0 = __ldg(p0 + lane);
            float4 x1 = __ldg(p1 + lane);
            float4 x2 = __ldg(p2 + lane);
            float4 x3 = __ldg(p3 + lane);
            acc.x = fmaf(v0, x0.x, acc.x); acc.y = fmaf(v0, x0.y, acc.y);
            acc.z = fmaf(v0, x0.z, acc.z); acc.w = fmaf(v0, x0.w, acc.w);
            acc.x = fmaf(v1, x1.x, acc.x); acc.y = fmaf(v1, x1.y, acc.y);
            acc.z = fmaf(v1, x1.z, acc.z); acc.w = fmaf(v1, x1.w, acc.w);
            acc.x = fmaf(v2, x2.x, acc.x); acc.y = fmaf(v2, x2.y, acc.y);
            acc.z = fmaf(v2, x2.z, acc.z); acc.w = fmaf(v2, x2.w, acc.w);
            acc.x = fmaf(v3, x3.x, acc.x); acc.y = fmaf(v3, x3.y, acc.y);
            acc.z = fmaf(v3, x3.z, acc.z); acc.w = fmaf(v3, x3.w, acc.w);
        }
        for (; j < cnt; ++j) {
            int   cj = __shfl_sync(0xffffffffu, c, j);
            float vj = __shfl_sync(0xffffffffu, v, j);
            const float4* pj = (cj < split) ? (srcU + (long long)cj * 32)
                                            : (srcI + (long long)(cj - split) * 32);
            float4 x = __ldg(pj + lane);
            acc.x = fmaf(vj, x.x, acc.x);
            acc.y = fmaf(vj, x.y, acc.y);
            acc.z = fmaf(vj, x.z, acc.z);
            acc.w = fmaf(vj, x.w, acc.w);
        }
    }
    dst[w * 32 + lane] = acc;
}

// users/items may be int32 or int64 (JAX x64 ambiguity): detect on device.
__device__ __forceinline__ bool is_i64(const int* p) {
    bool z = true;
    #pragma unroll
    for (int j = 1; j < 64; j += 2) z = z && (p[j] == 0);
    return z;
}

// Gather + 0.25*add into out. which: 0 = raw inputs (split), 1 = g_Y, 2 = g_X.
__global__ void k_gather(const int* __restrict__ users, const int* __restrict__ items,
                         const float4* __restrict__ embU, const float4* __restrict__ embI,
                         int which, float4* __restrict__ out, int init) {
    int w = (blockIdx.x * blockDim.x + threadIdx.x) >> 5;
    int lane = threadIdx.x & 31;
    if (w >= 2 * BATCHQ) return;

    const float4* srcU;
    const float4* srcI;
    int split;
    if (which == 0) { srcU = embU; srcI = embI; split = U_COUNT; }
    else if (which == 1) {
        srcU = reinterpret_cast<const float4*>(g_Y); srcI = srcU; split = NN;
    } else {
        srcU = reinterpret_cast<const float4*>(g_X); srcI = srcU; split = NN;
    }

    int node;
    if (w < BATCHQ) {
        bool w64 = is_i64(users);
        node = w64 ? users[2 * w] : users[w];
    } else {
        int idx = w - BATCHQ;
        bool w64 = is_i64(items);
        node = U_COUNT + (w64 ? items[2 * idx] : items[idx]);
    }
    node = max(0, min(NN - 1, node));
    const float4* p = (node < split) ? (srcU + (long long)node * 32)
                                     : (srcI + (long long)(node - split) * 32);
    float4 v = p[lane];
    float4 o = init ? make_float4(0.f, 0.f, 0.f, 0.f) : out[w * 32 + lane];
    o.x += 0.25f * v.x;
    o.y += 0.25f * v.y;
    o.z += 0.25f * v.z;
    o.w += 0.25f * v.w;
    out[w * 32 + lane] = o;
}

extern "C" void kernel_launch(void* const* d_in, const int* in_sizes, int n_in,
                              void* d_out, int out_size) {
    const float4* user_emb = (const float4*)d_in[0];
    const float4* item_emb = (const float4*)d_in[1];
    const float*  adj_vals = (const float*)d_in[2];
    const int*    adj_rows = (const int*)d_in[3];
    const int*    adj_cols = (const int*)d_in[4];
    const int*    users    = (const int*)d_in[5];
    const int*    items    = (const int*)d_in[6];
    float4*       out      = (float4*)d_out;

    const int T = 256;

    // CSR build
    k_zero_counts<<<(N_PAD + T - 1) / T, T>>>();
    k_hist<<<(NNZ_C + T - 1) / T, T>>>(adj_rows);
    k_scan_part<<<NBLK_SCAN, 1024>>>();
    k_scan_add<<<NBLK_SCAN, 1024>>>();
    k_scatter<<<(NNZ_C + T - 1) / T, T>>>(adj_rows, adj_cols, adj_vals);

    const int GATHER_BLOCKS = (2 * BATCHQ * 32 + T - 1) / T;
    const int SPMM_BLOCKS   = (NN * 32 + T - 1) / T;

    // layer 0 (ego itself) — read raw inputs
    k_gather<<<GATHER_BLOCKS, T>>>(users, items, user_emb, item_emb, 0, out, 1);
    // layer 1: inputs -> Y
    k_spmm<<<SPMM_BLOCKS, T>>>(user_emb, item_emb, 0);
    k_gather<<<GATHER_BLOCKS, T>>>(users, items, user_emb, item_emb, 1, out, 0);
    // layer 2: Y -> X
    k_spmm<<<SPMM_BLOCKS, T>>>(user_emb, item_emb, 1);
    k_gather<<<GATHER_BLOCKS, T>>>(users, items, user_emb, item_emb, 2, out, 0);
    // layer 3: X -> Y
    k_spmm<<<SPMM_BLOCKS, T>>>(user_emb, item_emb, 2);
    k_gather<<<GATHER_BLOCKS, T>>>(users, items, user_emb, item_emb, 1, out, 0);
}